// round 12
// baseline (speedup 1.0000x reference)
#include <cuda_runtime.h>
#include <cstdint>

#define BATCH 64
#define NSTEPS 2000
#define TAPS 64
#define NTHREADS 256
#define CHUNK 16
#define NCHUNK (NSTEPS / CHUNK)   // 125
#define SYM_CHUNKS 6              // symmetrize every 96 steps

using ull = unsigned long long;

__device__ __forceinline__ void cp16(uint32_t dst_smem, const void* src_gmem) {
    asm volatile("cp.async.cg.shared.global [%0], [%1], 16;\n"
                 :: "r"(dst_smem), "l"(src_gmem));
}
__device__ __forceinline__ void cp_commit() {
    asm volatile("cp.async.commit_group;\n");
}
template <int N>
__device__ __forceinline__ void cp_wait() {
    asm volatile("cp.async.wait_group %0;\n" :: "n"(N));
}

// ---- packed f32x2 ops (Blackwell sm_103a) ----
__device__ __forceinline__ ull ffma2(ull a, ull b, ull c) {
    ull d; asm("fma.rn.f32x2 %0, %1, %2, %3;" : "=l"(d) : "l"(a), "l"(b), "l"(c));
    return d;
}
__device__ __forceinline__ ull fadd2(ull a, ull b) {
    ull d; asm("add.rn.f32x2 %0, %1, %2;" : "=l"(d) : "l"(a), "l"(b));
    return d;
}
__device__ __forceinline__ ull pack2(float x) {
    ull d; uint32_t t = __float_as_uint(x);
    asm("mov.b64 %0, {%1, %2};" : "=l"(d) : "r"(t), "r"(t));
    return d;
}
__device__ __forceinline__ ull pack2two(float a, float b) {
    ull d;
    asm("mov.b64 %0, {%1, %2};" : "=l"(d)
        : "r"(__float_as_uint(a)), "r"(__float_as_uint(b)));
    return d;
}
__device__ __forceinline__ void unpack2(ull v, float& a, float& b) {
    uint32_t lo, hi;
    asm("mov.b64 {%0, %1}, %2;" : "=r"(lo), "=r"(hi) : "l"(v));
    a = __uint_as_float(lo); b = __uint_as_float(hi);
}
__device__ __forceinline__ float hadd2(ull v) {
    float a, b; unpack2(v, a, b); return a + b;
}

__global__ void __launch_bounds__(NTHREADS, 1)
rls_kernel(const float* __restrict__ x_seq,
           const float* __restrict__ d_seq,
           const float* __restrict__ lambdas,
           float* __restrict__ y_out,
           float* __restrict__ w_out)
{
    const int b   = blockIdx.x;
    const int tid = threadIdx.x;
    const int i   = tid >> 2;   // row 0..63
    const int q   = tid & 3;    // column quarter 0..3 -> cols [16q, 16q+16)

    __shared__ __align__(16) float xc[4][CHUNK][TAPS];   // rotating chunk bufs
    __shared__ __align__(16) float dc[4][CHUNK];
    __shared__ __align__(16) float lc[4][CHUNK];
    __shared__ __align__(16) float Uxbuf[2][TAPS];
    __shared__ float tile[TAPS][TAPS + 1];

    // packed state: 8 x f32x2 = this thread's 16-col quarter of each vector
    ull Q2[8];   // row i of Q (P = sigma * Q), cols [16q, 16q+16)
    ull w2[8];   // w quarter (redundant across rows)
    ull u2[8];   // u_t quarter
    ull xa[8];   // x buffer A
    ull xb[8];   // x buffer B
#pragma unroll
    for (int k = 0; k < 8; k++) {
        const int j0 = q * 16 + 2 * k;
        Q2[k] = pack2two(i == j0 ? 1.0f : 0.0f, i == j0 + 1 ? 1.0f : 0.0f);
        w2[k] = 0ull;
    }
    float sigma = 1.0f;
    float y     = 0.0f;
    float delta = 0.0f;          // w_{t}' x_{t+1}, carried
    float Uxi, Vxi;

    const float* xgb = x_seq + (size_t)b * NSTEPS * TAPS;
    const float* dgb = d_seq + (size_t)b * NSTEPS;

    const uint32_t xc_s = (uint32_t)__cvta_generic_to_shared(&xc[0][0][0]);
    const uint32_t dc_s = (uint32_t)__cvta_generic_to_shared(&dc[0][0]);
    const uint32_t lc_s = (uint32_t)__cvta_generic_to_shared(&lc[0][0]);

    auto issue_chunk = [&](int ck, int cb) {
        cp16(xc_s + (uint32_t)(cb * (CHUNK * TAPS)) * 4 + tid * 16,
             xgb + (size_t)ck * CHUNK * TAPS + tid * 4);
        if (tid < 4)
            cp16(dc_s + (uint32_t)(cb * CHUNK) * 4 + tid * 16,
                 dgb + ck * CHUNK + tid * 4);
        else if (tid < 8)
            cp16(lc_s + (uint32_t)(cb * CHUNK) * 4 + (tid - 4) * 16,
                 lambdas + ck * CHUNK + (tid - 4) * 4);
        cp_commit();
    };

    issue_chunk(0, 0);
    issue_chunk(1, 1);
    cp_wait<1>();
    __syncthreads();

    // ---- bootstrap: u_0 = x_0 (Q = I); v_0 = Q_0 x_1 = x_1 ----
    Uxi = xc[0][0][i];
    if (q == 0) Uxbuf[0][i] = Uxi;
    Vxi = xc[0][1][i];
#pragma unroll
    for (int k = 0; k < 4; k++) {
        const ulonglong2 va = *(const ulonglong2*)(&xc[0][0][q * 16 + 4 * k]);
        xa[2 * k] = va.x; xa[2 * k + 1] = va.y;
        const ulonglong2 vb = *(const ulonglong2*)(&xc[0][1][q * 16 + 4 * k]);
        xb[2 * k] = vb.x; xb[2 * k + 1] = vb.y;
    }
    float d_cur = dc[0][0], lam_cur = lc[0][0];

    // one RLS step; xcur = x_t quarter, xnxt = x_{t+1} quarter.
    // tail loads x_{t+2} into xcur (x_t dead) -> roles swap next step.
    auto step = [&](int t, ull (&xcur)[8], ull (&xnxt)[8]) {
        const int rb = t & 1;                   // Uxbuf slot holding u_t

        // ---- post-barrier: load u_t quarter; dots gam = u'x_{t+1}, alpha = u'x_t ----
        ull g0 = 0ull, g1 = 0ull, a0 = 0ull, a1 = 0ull;
#pragma unroll
        for (int k = 0; k < 4; k++) {
            const ulonglong2 uu = *(const ulonglong2*)(&Uxbuf[rb][q * 16 + 4 * k]);
            u2[2 * k] = uu.x; u2[2 * k + 1] = uu.y;
            g0 = ffma2(uu.x, xnxt[2 * k],     g0);
            g1 = ffma2(uu.y, xnxt[2 * k + 1], g1);
            a0 = ffma2(uu.x, xcur[2 * k],     a0);
            a1 = ffma2(uu.y, xcur[2 * k + 1], a1);
        }
        float gh = hadd2(fadd2(g0, g1));
        float ah = hadd2(fadd2(a0, a1));
        gh += __shfl_xor_sync(0xffffffffu, gh, 1);
        ah += __shfl_xor_sync(0xffffffffu, ah, 1);
        gh += __shfl_xor_sync(0xffffffffu, gh, 2);
        ah += __shfl_xor_sync(0xffffffffu, ah, 2);
        const float gam = gh, alpha = ah;

        // ---- scalars ----
        const float lam   = fminf(fmaxf(lam_cur, 1e-4f), 0.9999f);
        const float denom = fmaf(sigma, alpha, lam);
        const float kk    = sigma * __fdividef(1.0f, denom);
        const float e     = d_cur - y;
        if (tid == 0) y_out[(size_t)b * NSTEPS + t] = y;
        const float ke = kk * e;
        y = fmaf(ke, gam, delta);               // y_{t+1}
        sigma = sigma / lam;                    // exact div (error never damps)

        // ---- publish u_{t+1} (gates the barrier) ----
        const float unew = fmaf(-kk * gam, Uxi, Vxi);
        if (q == 0) Uxbuf[rb ^ 1][i] = unew;

        // ---- Q_{t+1} = Q_t - kk u_t u_t'; w_{t+1} = w_t + ke u_t ----
        const ull mq  = pack2(-kk * Uxi);
        const ull ke2 = pack2(ke);
#pragma unroll
        for (int k = 0; k < 8; k++) {
            Q2[k] = ffma2(mq,  u2[k], Q2[k]);
            w2[k] = ffma2(ke2, u2[k], w2[k]);
        }
        Uxi = unew;

        // ---- prefetch next scalars ----
        const int t1 = (t + 1 < NSTEPS) ? t + 1 : t;
        d_cur   = dc[(t1 >> 4) & 3][t1 & (CHUNK - 1)];
        lam_cur = lc[(t1 >> 4) & 3][t1 & (CHUNK - 1)];

        // ---- tail: load x_{t+2} into xcur; v_{t+1} = Q_{t+1}x_{t+2}; delta ----
        const int t2  = (t + 2 < NSTEPS) ? t + 2 : NSTEPS - 1;
        const int cb2 = (t2 >> 4) & 3, sl2 = t2 & (CHUNK - 1);
#pragma unroll
        for (int k = 0; k < 4; k++) {
            const ulonglong2 v = *(const ulonglong2*)(&xc[cb2][sl2][q * 16 + 4 * k]);
            xcur[2 * k] = v.x; xcur[2 * k + 1] = v.y;
        }
        ull m0 = 0ull, m1 = 0ull, dd0 = 0ull, dd1 = 0ull;
#pragma unroll
        for (int k = 0; k < 8; k += 2) {
            m0  = ffma2(Q2[k + 0], xcur[k + 0], m0);
            m1  = ffma2(Q2[k + 1], xcur[k + 1], m1);
            dd0 = ffma2(w2[k + 0], xcur[k + 0], dd0);
            dd1 = ffma2(w2[k + 1], xcur[k + 1], dd1);
        }
        float vh = hadd2(fadd2(m0, m1));
        float dh = hadd2(fadd2(dd0, dd1));
        vh += __shfl_xor_sync(0xffffffffu, vh, 1);
        dh += __shfl_xor_sync(0xffffffffu, dh, 1);
        vh += __shfl_xor_sync(0xffffffffu, vh, 2);
        dh += __shfl_xor_sync(0xffffffffu, dh, 2);
        Vxi = vh; delta = dh;

        __syncthreads();   // the one per-step barrier
    };

    for (int ck = 0; ck < NCHUNK; ck++) {
        if (ck + 2 < NCHUNK) { issue_chunk(ck + 2, (ck + 2) & 3); cp_wait<1>(); }
        else                 { cp_wait<0>(); }
        __syncthreads();

#pragma unroll 2
        for (int s = 0; s < CHUNK; s += 2) {
            const int t = ck * CHUNK + s;
            step(t,     xa, xb);    // enters with xa=x_t,   xb=x_{t+1}; exits xa=x_{t+2}
            step(t + 1, xb, xa);    // enters with xb=x_{t+1}, xa=x_{t+2}; exits xb=x_{t+3}
        }

        // ---- symmetrize every SYM_CHUNKS chunks (kills undamped antisym mode) ----
        if ((ck % SYM_CHUNKS) == (SYM_CHUNKS - 1)) {
#pragma unroll
            for (int k = 0; k < 8; k++) {
                float f0, f1; unpack2(Q2[k], f0, f1);
                tile[i][q * 16 + 2 * k]     = f0;
                tile[i][q * 16 + 2 * k + 1] = f1;
            }
            __syncthreads();
#pragma unroll
            for (int k = 0; k < 8; k++) {
                float f0, f1; unpack2(Q2[k], f0, f1);
                const float t0 = tile[q * 16 + 2 * k][i];
                const float t1 = tile[q * 16 + 2 * k + 1][i];
                Q2[k] = pack2two(0.5f * (f0 + t0), 0.5f * (f1 + t1));
            }
            __syncthreads();
        }
    }

    // ---- outputs: w (tids 0..3 write their quarters of batch b) ----
    if (i == 0) {
#pragma unroll
        for (int k = 0; k < 8; k++) {
            float f0, f1; unpack2(w2[k], f0, f1);
            w_out[(size_t)b * TAPS + q * 16 + 2 * k]     = f0;
            w_out[(size_t)b * TAPS + q * 16 + 2 * k + 1] = f1;
        }
    }
}

extern "C" void kernel_launch(void* const* d_in, const int* in_sizes, int n_in,
                              void* d_out, int out_size)
{
    const float* x_seq   = (const float*)d_in[0];
    const float* d_seq   = (const float*)d_in[1];
    const float* lambdas = (const float*)d_in[2];
    float* y_out = (float*)d_out;                          // [64, 2000]
    float* w_out = (float*)d_out + (size_t)BATCH * NSTEPS; // [64, 64]
    rls_kernel<<<BATCH, NTHREADS>>>(x_seq, d_seq, lambdas, y_out, w_out);
}

// round 13
// speedup vs baseline: 1.3736x; 1.3736x over previous
#include <cuda_runtime.h>
#include <cstdint>

#define BATCH 64
#define NSTEPS 2000
#define TAPS 64
#define NTHREADS 128
#define CHUNK 16
#define NCHUNK (NSTEPS / CHUNK)   // 125
#define SYM_CHUNKS 6              // symmetrize every 96 steps

using ull = unsigned long long;

__device__ __forceinline__ void cp16(uint32_t dst_smem, const void* src_gmem) {
    asm volatile("cp.async.cg.shared.global [%0], [%1], 16;\n"
                 :: "r"(dst_smem), "l"(src_gmem));
}
__device__ __forceinline__ void cp_commit() {
    asm volatile("cp.async.commit_group;\n");
}
template <int N>
__device__ __forceinline__ void cp_wait() {
    asm volatile("cp.async.wait_group %0;\n" :: "n"(N));
}

// ---- packed f32x2 ops (Blackwell sm_103a) ----
__device__ __forceinline__ ull ffma2(ull a, ull b, ull c) {
    ull d; asm("fma.rn.f32x2 %0, %1, %2, %3;" : "=l"(d) : "l"(a), "l"(b), "l"(c));
    return d;
}
__device__ __forceinline__ ull fadd2(ull a, ull b) {
    ull d; asm("add.rn.f32x2 %0, %1, %2;" : "=l"(d) : "l"(a), "l"(b));
    return d;
}
__device__ __forceinline__ ull pack2(float x) {
    ull d; uint32_t t = __float_as_uint(x);
    asm("mov.b64 %0, {%1, %2};" : "=l"(d) : "r"(t), "r"(t));
    return d;
}
__device__ __forceinline__ ull pack2two(float a, float b) {
    ull d;
    asm("mov.b64 %0, {%1, %2};" : "=l"(d)
        : "r"(__float_as_uint(a)), "r"(__float_as_uint(b)));
    return d;
}
__device__ __forceinline__ void unpack2(ull v, float& a, float& b) {
    uint32_t lo, hi;
    asm("mov.b64 {%0, %1}, %2;" : "=r"(lo), "=r"(hi) : "l"(v));
    a = __uint_as_float(lo); b = __uint_as_float(hi);
}
__device__ __forceinline__ float hadd2(ull v) {
    float a, b; unpack2(v, a, b); return a + b;
}

__global__ void __launch_bounds__(NTHREADS, 1)
rls_kernel(const float* __restrict__ x_seq,
           const float* __restrict__ d_seq,
           const float* __restrict__ lambdas,
           float* __restrict__ y_out,
           float* __restrict__ w_out)
{
    const int b   = blockIdx.x;
    const int tid = threadIdx.x;
    const int i   = tid >> 1;   // row 0..63
    const int c   = tid & 1;    // column-half 0/1

    __shared__ __align__(16) float xc[4][CHUNK][TAPS];   // rotating chunk bufs
    __shared__ __align__(16) float dc[4][CHUNK];
    __shared__ __align__(16) float lc[4][CHUNK];
    __shared__ __align__(16) float u1buf[2][TAPS];
    __shared__ __align__(16) float u2buf[2][TAPS];
    __shared__ float tile[TAPS][TAPS + 1];

    // packed state: 16 x f32x2 = this thread's 32-col half. P = sigma * Q.
    ull Q2[16];   // row i of Q, cols [32c, 32c+32)
    ull w2[16];   // w half (redundant across rows)
#pragma unroll
    for (int k = 0; k < 16; k++) {
        const int j0 = c * 32 + 2 * k;
        Q2[k] = pack2two(i == j0 ? 1.0f : 0.0f, i == j0 + 1 ? 1.0f : 0.0f);
        w2[k] = 0ull;
    }
    float sigma = 1.0f;

    const float* xgb = x_seq + (size_t)b * NSTEPS * TAPS;
    const float* dgb = d_seq + (size_t)b * NSTEPS;
    float* yo = y_out + (size_t)b * NSTEPS;

    const uint32_t xc_s = (uint32_t)__cvta_generic_to_shared(&xc[0][0][0]);
    const uint32_t dc_s = (uint32_t)__cvta_generic_to_shared(&dc[0][0]);
    const uint32_t lc_s = (uint32_t)__cvta_generic_to_shared(&lc[0][0]);

    auto issue_chunk = [&](int ck, int cb) {
#pragma unroll
        for (int j = 0; j < 2; j++)
            cp16(xc_s + (uint32_t)(cb * (CHUNK * TAPS) + j * 512) * 4 + tid * 16,
                 xgb + (size_t)ck * CHUNK * TAPS + j * 512 + tid * 4);
        if (tid < 4)
            cp16(dc_s + (uint32_t)(cb * CHUNK) * 4 + tid * 16,
                 dgb + ck * CHUNK + tid * 4);
        else if (tid < 8)
            cp16(lc_s + (uint32_t)(cb * CHUNK) * 4 + (tid - 4) * 16,
                 lambdas + ck * CHUNK + (tid - 4) * 4);
        cp_commit();
    };

    issue_chunk(0, 0);
    issue_chunk(1, 1);
    cp_wait<1>();
    __syncthreads();

    for (int ck = 0; ck < NCHUNK; ck++) {
        if (ck + 2 < NCHUNK) { issue_chunk(ck + 2, (ck + 2) & 3); cp_wait<1>(); }
        else                 { cp_wait<0>(); }
        __syncthreads();
        const int cb = ck & 3;

        // 8 rank-2 blocks per chunk (steps 2m, 2m+1)
#pragma unroll 2
        for (int blk = 0; blk < CHUNK / 2; blk++) {
            const int s  = 2 * blk;
            const int t  = ck * CHUNK + s;
            const int pb = blk & 1;              // u-buf ping-pong

            const float* x1p = &xc[cb][s][c * 32];
            const float* x2p = &xc[cb][s + 1][c * 32];

            // ===== Phase A: matvecs u1 = Q x1, u2p = Q x2; w-dots y1, del2 =====
            ull p1a = 0ull, p1b = 0ull, p2a = 0ull, p2b = 0ull;
            ull ya = 0ull, yb = 0ull, da = 0ull, db2 = 0ull;
#pragma unroll
            for (int k = 0; k < 8; k++) {
                const ulonglong2 v1 = *(const ulonglong2*)(x1p + 4 * k);
                const ulonglong2 v2 = *(const ulonglong2*)(x2p + 4 * k);
                p1a = ffma2(Q2[2 * k],     v1.x, p1a);
                p1b = ffma2(Q2[2 * k + 1], v1.y, p1b);
                p2a = ffma2(Q2[2 * k],     v2.x, p2a);
                p2b = ffma2(Q2[2 * k + 1], v2.y, p2b);
                ya  = ffma2(w2[2 * k],     v1.x, ya);
                yb  = ffma2(w2[2 * k + 1], v1.y, yb);
                da  = ffma2(w2[2 * k],     v2.x, da);
                db2 = ffma2(w2[2 * k + 1], v2.y, db2);
            }
            float u1i  = hadd2(fadd2(p1a, p1b));
            float u2pi = hadd2(fadd2(p2a, p2b));
            float y1   = hadd2(fadd2(ya,  yb));
            float del2 = hadd2(fadd2(da,  db2));
            u1i  += __shfl_xor_sync(0xffffffffu, u1i,  1);
            u2pi += __shfl_xor_sync(0xffffffffu, u2pi, 1);
            y1   += __shfl_xor_sync(0xffffffffu, y1,   1);
            del2 += __shfl_xor_sync(0xffffffffu, del2, 1);
            if (c == 0) { u1buf[pb][i] = u1i; u2buf[pb][i] = u2pi; }

            const float d1  = dc[cb][s],     d2  = dc[cb][s + 1];
            const float l1r = lc[cb][s],     l2r = lc[cb][s + 1];

            __syncthreads();   // the ONE barrier per 2 steps

            // ===== Phase B: dots alpha1, gamma, beta; scalars; rank-2 update =====
            ull u1h[16], u2h[16];
            ull aa = 0ull, ab = 0ull, ga = 0ull, gb = 0ull, ba = 0ull, bb = 0ull;
#pragma unroll
            for (int k = 0; k < 8; k++) {
                const ulonglong2 uu1 = *(const ulonglong2*)(&u1buf[pb][c * 32 + 4 * k]);
                const ulonglong2 uu2 = *(const ulonglong2*)(&u2buf[pb][c * 32 + 4 * k]);
                const ulonglong2 v1  = *(const ulonglong2*)(x1p + 4 * k);
                const ulonglong2 v2  = *(const ulonglong2*)(x2p + 4 * k);
                u1h[2 * k] = uu1.x; u1h[2 * k + 1] = uu1.y;
                u2h[2 * k] = uu2.x; u2h[2 * k + 1] = uu2.y;
                aa = ffma2(uu1.x, v1.x, aa); ab = ffma2(uu1.y, v1.y, ab);
                ga = ffma2(uu1.x, v2.x, ga); gb = ffma2(uu1.y, v2.y, gb);
                ba = ffma2(uu2.x, v2.x, ba); bb = ffma2(uu2.y, v2.y, bb);
            }
            float al1 = hadd2(fadd2(aa, ab));
            float gam = hadd2(fadd2(ga, gb));
            float bet = hadd2(fadd2(ba, bb));
            al1 += __shfl_xor_sync(0xffffffffu, al1, 1);
            gam += __shfl_xor_sync(0xffffffffu, gam, 1);
            bet += __shfl_xor_sync(0xffffffffu, bet, 1);

            // scalars (k-divs fast: error Riccati-damped; sigma-div exact)
            const float l1 = fminf(fmaxf(l1r, 1e-4f), 0.9999f);
            const float l2 = fminf(fmaxf(l2r, 1e-4f), 0.9999f);
            const float k1   = sigma * __fdividef(1.0f, fmaf(sigma, al1, l1));
            const float e1   = d1 - y1;
            const float k1e1 = k1 * e1;
            const float y2   = fmaf(k1e1, gam, del2);
            const float e2   = d2 - y2;
            const float k1g  = k1 * gam;
            const float al2  = fmaf(-k1g, gam, bet);
            const float ll   = l1 * l2;
            const float k2   = sigma * __fdividef(1.0f, fmaf(sigma, al2, ll));
            const float k2e2 = k2 * e2;
            sigma = sigma / ll;
            if (tid == 0) { yo[t] = y1; yo[t + 1] = y2; }

            const float u2i = fmaf(-k1g, u1i, u2pi);
            const ull c_u2 = pack2(-k1g);
            const ull c_q1 = pack2(-k1 * u1i);
            const ull c_q2 = pack2(-k2 * u2i);
            const ull c_w1 = pack2(k1e1);
            const ull c_w2 = pack2(k2e2);
#pragma unroll
            for (int k = 0; k < 16; k++) {
                u2h[k] = ffma2(c_u2, u1h[k], u2h[k]);        // u2 = u2p - k1*gam*u1
                Q2[k]  = ffma2(c_q1, u1h[k], Q2[k]);         // Q -= k1 u1 u1'
                Q2[k]  = ffma2(c_q2, u2h[k], Q2[k]);         // Q -= k2 u2 u2'
                w2[k]  = ffma2(c_w1, u1h[k], w2[k]);         // w += k1 e1 u1
                w2[k]  = ffma2(c_w2, u2h[k], w2[k]);         // w += k2 e2 u2
            }
        }

        // ---- symmetrize every SYM_CHUNKS chunks (kills undamped antisym mode) ----
        if ((ck % SYM_CHUNKS) == (SYM_CHUNKS - 1)) {
            __syncthreads();   // all phase-B u-buf reads done before tile reuse
#pragma unroll
            for (int k = 0; k < 16; k++) {
                float f0, f1; unpack2(Q2[k], f0, f1);
                tile[i][c * 32 + 2 * k]     = f0;
                tile[i][c * 32 + 2 * k + 1] = f1;
            }
            __syncthreads();
#pragma unroll
            for (int k = 0; k < 16; k++) {
                float f0, f1; unpack2(Q2[k], f0, f1);
                const float t0 = tile[c * 32 + 2 * k][i];
                const float t1 = tile[c * 32 + 2 * k + 1][i];
                Q2[k] = pack2two(0.5f * (f0 + t0), 0.5f * (f1 + t1));
            }
            __syncthreads();
        }
    }

    // ---- outputs: w (tid 0 writes half c=0, tid 1 writes half c=1) ----
    if (i == 0) {
#pragma unroll
        for (int k = 0; k < 16; k++) {
            float f0, f1; unpack2(w2[k], f0, f1);
            w_out[(size_t)b * TAPS + c * 32 + 2 * k]     = f0;
            w_out[(size_t)b * TAPS + c * 32 + 2 * k + 1] = f1;
        }
    }
}

extern "C" void kernel_launch(void* const* d_in, const int* in_sizes, int n_in,
                              void* d_out, int out_size)
{
    const float* x_seq   = (const float*)d_in[0];
    const float* d_seq   = (const float*)d_in[1];
    const float* lambdas = (const float*)d_in[2];
    float* y_out = (float*)d_out;                          // [64, 2000]
    float* w_out = (float*)d_out + (size_t)BATCH * NSTEPS; // [64, 64]
    rls_kernel<<<BATCH, NTHREADS>>>(x_seq, d_seq, lambdas, y_out, w_out);
}

// round 14
// speedup vs baseline: 1.6273x; 1.1847x over previous
#include <cuda_runtime.h>
#include <cstdint>

#define BATCH 64
#define NSTEPS 2000
#define TAPS 64
#define NTHREADS 128
#define CHUNK 16
#define NCHUNK (NSTEPS / CHUNK)   // 125
#define SYM_CHUNKS 6              // symmetrize every 96 steps

using ull = unsigned long long;

__device__ __forceinline__ void cp16(uint32_t dst_smem, const void* src_gmem) {
    asm volatile("cp.async.cg.shared.global [%0], [%1], 16;\n"
                 :: "r"(dst_smem), "l"(src_gmem));
}
__device__ __forceinline__ void cp_commit() {
    asm volatile("cp.async.commit_group;\n");
}
template <int N>
__device__ __forceinline__ void cp_wait() {
    asm volatile("cp.async.wait_group %0;\n" :: "n"(N));
}

// ---- packed f32x2 ops (Blackwell sm_103a) ----
__device__ __forceinline__ ull ffma2(ull a, ull b, ull c) {
    ull d; asm("fma.rn.f32x2 %0, %1, %2, %3;" : "=l"(d) : "l"(a), "l"(b), "l"(c));
    return d;
}
__device__ __forceinline__ ull fadd2(ull a, ull b) {
    ull d; asm("add.rn.f32x2 %0, %1, %2;" : "=l"(d) : "l"(a), "l"(b));
    return d;
}
__device__ __forceinline__ ull pack2(float x) {
    ull d; uint32_t t = __float_as_uint(x);
    asm("mov.b64 %0, {%1, %2};" : "=l"(d) : "r"(t), "r"(t));
    return d;
}
__device__ __forceinline__ ull pack2two(float a, float b) {
    ull d;
    asm("mov.b64 %0, {%1, %2};" : "=l"(d)
        : "r"(__float_as_uint(a)), "r"(__float_as_uint(b)));
    return d;
}
__device__ __forceinline__ void unpack2(ull v, float& a, float& b) {
    uint32_t lo, hi;
    asm("mov.b64 {%0, %1}, %2;" : "=r"(lo), "=r"(hi) : "l"(v));
    a = __uint_as_float(lo); b = __uint_as_float(hi);
}
__device__ __forceinline__ float hadd2(ull v) {
    float a, b; unpack2(v, a, b); return a + b;
}

__global__ void __launch_bounds__(NTHREADS, 1)
rls_kernel(const float* __restrict__ x_seq,
           const float* __restrict__ d_seq,
           const float* __restrict__ lambdas,
           float* __restrict__ y_out,
           float* __restrict__ w_out)
{
    const int b    = blockIdx.x;
    const int tid  = threadIdx.x;
    const int i    = tid >> 1;   // row 0..63
    const int c    = tid & 1;    // column-half 0/1 (== lane parity)
    const int lane = tid & 31;
    const int warp = tid >> 5;

    __shared__ __align__(16) float xc[4][CHUNK][TAPS];   // rotating chunk bufs
    __shared__ __align__(16) float dc[4][CHUNK];
    __shared__ __align__(16) float lc[4][CHUNK];
    __shared__ __align__(16) float u1buf[2][TAPS];
    __shared__ __align__(16) float u2buf[2][TAPS];
    __shared__ __align__(16) float4 redA[2][4];          // {alpha, beta, y1, -} per warp
    __shared__ __align__(8)  float2 redG[2][4];          // {gamma, delta2} per warp
    __shared__ float tile[TAPS][TAPS + 1];

    // Q row-half packed: 16 x f32x2 (cols [32c,32c+32)).  P = Q / rho.
    ull Q2[16];
#pragma unroll
    for (int k = 0; k < 16; k++) {
        const int j0 = c * 32 + 2 * k;
        Q2[k] = pack2two(i == j0 ? 1.0f : 0.0f, i == j0 + 1 ? 1.0f : 0.0f);
    }
    float wi  = 0.0f;    // w_i (row scalar; identical on both c threads)
    float rho = 1.0f;    // rho = prod(lambda) = 1/sigma

    const float* xgb = x_seq + (size_t)b * NSTEPS * TAPS;
    const float* dgb = d_seq + (size_t)b * NSTEPS;
    float* yo = y_out + (size_t)b * NSTEPS;

    const uint32_t xc_s = (uint32_t)__cvta_generic_to_shared(&xc[0][0][0]);
    const uint32_t dc_s = (uint32_t)__cvta_generic_to_shared(&dc[0][0]);
    const uint32_t lc_s = (uint32_t)__cvta_generic_to_shared(&lc[0][0]);

    auto issue_chunk = [&](int ck, int cb) {
#pragma unroll
        for (int j = 0; j < 2; j++)
            cp16(xc_s + (uint32_t)(cb * (CHUNK * TAPS) + j * 512) * 4 + tid * 16,
                 xgb + (size_t)ck * CHUNK * TAPS + j * 512 + tid * 4);
        if (tid < 4)
            cp16(dc_s + (uint32_t)(cb * CHUNK) * 4 + tid * 16,
                 dgb + ck * CHUNK + tid * 4);
        else if (tid < 8)
            cp16(lc_s + (uint32_t)(cb * CHUNK) * 4 + (tid - 4) * 16,
                 lambdas + ck * CHUNK + (tid - 4) * 4);
        cp_commit();
    };

    issue_chunk(0, 0);
    issue_chunk(1, 1);
    cp_wait<1>();
    __syncthreads();

    for (int ck = 0; ck < NCHUNK; ck++) {
        if (ck + 2 < NCHUNK) { issue_chunk(ck + 2, (ck + 2) & 3); cp_wait<1>(); }
        else                 { cp_wait<0>(); }
        __syncthreads();
        const int cb = ck & 3;

#pragma unroll 4
        for (int blk = 0; blk < CHUNK / 2; blk++) {
            const int s  = 2 * blk;
            const int t  = ck * CHUNK + s;
            const int pb = blk & 1;

            const float* x1p = &xc[cb][s][0];
            const float* x2p = &xc[cb][s + 1][0];

            // ===== Phase A: matvecs u1 = Q x1, u2p = Q x2 =====
            ull p1a = 0ull, p1b = 0ull, p2a = 0ull, p2b = 0ull;
#pragma unroll
            for (int k = 0; k < 8; k++) {
                const ulonglong2 v1 = *(const ulonglong2*)(x1p + c * 32 + 4 * k);
                const ulonglong2 v2 = *(const ulonglong2*)(x2p + c * 32 + 4 * k);
                p1a = ffma2(Q2[2 * k],     v1.x, p1a);
                p1b = ffma2(Q2[2 * k + 1], v1.y, p1b);
                p2a = ffma2(Q2[2 * k],     v2.x, p2a);
                p2b = ffma2(Q2[2 * k + 1], v2.y, p2b);
            }
            float u1i  = hadd2(fadd2(p1a, p1b));
            float u2pi = hadd2(fadd2(p2a, p2b));
            u1i  += __shfl_xor_sync(0xffffffffu, u1i,  1);
            u2pi += __shfl_xor_sync(0xffffffffu, u2pi, 1);
            if (c == 0) { u1buf[pb][i] = u1i; u2buf[pb][i] = u2pi; }

            // ===== scalar-product trees: even lanes {alpha,beta,y1}, odd {gamma,delta2} ====
            const float x1i = x1p[i];
            const float x2i = x2p[i];
            float t1 = (c == 0) ? u1i  * x1i : u1i * x2i;   // -> alpha | gamma
            float t2 = (c == 0) ? u2pi * x2i : wi  * x2i;   // -> beta  | delta2
            float t3 = (c == 0) ? wi   * x1i : 0.0f;        // -> y1    | (unused)
#pragma unroll
            for (int off = 16; off >= 2; off >>= 1) {
                t1 += __shfl_xor_sync(0xffffffffu, t1, off);
                t2 += __shfl_xor_sync(0xffffffffu, t2, off);
                t3 += __shfl_xor_sync(0xffffffffu, t3, off);
            }
            if (lane == 0) redA[pb][warp] = make_float4(t1, t2, t3, 0.0f);
            if (lane == 1) redG[pb][warp] = make_float2(t1, t2);

            const float d1  = dc[cb][s],  d2  = dc[cb][s + 1];
            const float l1r = lc[cb][s],  l2r = lc[cb][s + 1];

            __syncthreads();   // the ONE barrier per 2 steps

            // ===== Phase B: combine; scalars; rank-2 update =====
            const float4 A0 = redA[pb][0], A1 = redA[pb][1],
                         A2 = redA[pb][2], A3 = redA[pb][3];
            const float2 G0 = redG[pb][0], G1 = redG[pb][1],
                         G2 = redG[pb][2], G3 = redG[pb][3];
            const float al1 = (A0.x + A1.x) + (A2.x + A3.x);
            const float bet = (A0.y + A1.y) + (A2.y + A3.y);
            const float y1  = (A0.z + A1.z) + (A2.z + A3.z);
            const float gam = (G0.x + G1.x) + (G2.x + G3.x);
            const float de2 = (G0.y + G1.y) + (G2.y + G3.y);

            const float l1 = fminf(fmaxf(l1r, 1e-4f), 0.9999f);
            const float l2 = fminf(fmaxf(l2r, 1e-4f), 0.9999f);
            // k = sigma/(lam + sigma*alpha) == 1/(lam*rho + alpha)
            const float k1   = __fdividef(1.0f, fmaf(l1, rho, al1));
            const float e1   = d1 - y1;
            const float k1e1 = k1 * e1;
            const float y2   = fmaf(k1e1, gam, de2);
            const float e2   = d2 - y2;
            const float k1g  = k1 * gam;
            const float al2  = fmaf(-k1g, gam, bet);
            const float ll   = l1 * l2;
            const float k2   = __fdividef(1.0f, fmaf(ll, rho, al2));
            const float k2e2 = k2 * e2;
            rho *= ll;                             // 1/sigma update: one FMUL
            if (tid == 0) { yo[t] = y1; yo[t + 1] = y2; }

            // w_i row-scalar update (both c threads compute identically)
            const float u2i = fmaf(-k1g, u1i, u2pi);
            wi = fmaf(k1e1, u1i, wi);
            wi = fmaf(k2e2, u2i, wi);

            // Q -= k1 u1 u1' + k2 u2 u2'   (u vectors from smem, recombined)
            const ull c_u2 = pack2(-k1g);
            const ull c_q1 = pack2(-k1 * u1i);
            const ull c_q2 = pack2(-k2 * u2i);
#pragma unroll
            for (int k = 0; k < 8; k++) {
                const ulonglong2 uu1 = *(const ulonglong2*)(&u1buf[pb][c * 32 + 4 * k]);
                const ulonglong2 uu2 = *(const ulonglong2*)(&u2buf[pb][c * 32 + 4 * k]);
                const ull u2x = ffma2(c_u2, uu1.x, uu2.x);   // u2 = u2p - k1*gam*u1
                const ull u2y = ffma2(c_u2, uu1.y, uu2.y);
                Q2[2 * k]     = ffma2(c_q1, uu1.x, Q2[2 * k]);
                Q2[2 * k + 1] = ffma2(c_q1, uu1.y, Q2[2 * k + 1]);
                Q2[2 * k]     = ffma2(c_q2, u2x,  Q2[2 * k]);
                Q2[2 * k + 1] = ffma2(c_q2, u2y,  Q2[2 * k + 1]);
            }
        }

        // ---- symmetrize every SYM_CHUNKS chunks (kills undamped antisym mode) ----
        if ((ck % SYM_CHUNKS) == (SYM_CHUNKS - 1)) {
            __syncthreads();
#pragma unroll
            for (int k = 0; k < 16; k++) {
                float f0, f1; unpack2(Q2[k], f0, f1);
                tile[i][c * 32 + 2 * k]     = f0;
                tile[i][c * 32 + 2 * k + 1] = f1;
            }
            __syncthreads();
#pragma unroll
            for (int k = 0; k < 16; k++) {
                float f0, f1; unpack2(Q2[k], f0, f1);
                const float t0 = tile[c * 32 + 2 * k][i];
                const float t1 = tile[c * 32 + 2 * k + 1][i];
                Q2[k] = pack2two(0.5f * (f0 + t0), 0.5f * (f1 + t1));
            }
            __syncthreads();
        }
    }

    // ---- outputs: w_i row scalars ----
    if (c == 0) w_out[(size_t)b * TAPS + i] = wi;
}

extern "C" void kernel_launch(void* const* d_in, const int* in_sizes, int n_in,
                              void* d_out, int out_size)
{
    const float* x_seq   = (const float*)d_in[0];
    const float* d_seq   = (const float*)d_in[1];
    const float* lambdas = (const float*)d_in[2];
    float* y_out = (float*)d_out;                          // [64, 2000]
    float* w_out = (float*)d_out + (size_t)BATCH * NSTEPS; // [64, 64]
    rls_kernel<<<BATCH, NTHREADS>>>(x_seq, d_seq, lambdas, y_out, w_out);
}

// round 15
// speedup vs baseline: 1.8691x; 1.1486x over previous
#include <cuda_runtime.h>
#include <cstdint>

#define BATCH 64
#define NSTEPS 2000
#define TAPS 64
#define NTHREADS 128
#define CHUNK 16
#define NCHUNK (NSTEPS / CHUNK)   // 125
#define SYM_CHUNKS 6              // symmetrize every 96 steps

using ull = unsigned long long;

__device__ __forceinline__ void cp16(uint32_t dst_smem, const void* src_gmem) {
    asm volatile("cp.async.cg.shared.global [%0], [%1], 16;\n"
                 :: "r"(dst_smem), "l"(src_gmem));
}
__device__ __forceinline__ void cp_commit() {
    asm volatile("cp.async.commit_group;\n");
}
template <int N>
__device__ __forceinline__ void cp_wait() {
    asm volatile("cp.async.wait_group %0;\n" :: "n"(N));
}

// ---- packed f32x2 ops (Blackwell sm_103a) ----
__device__ __forceinline__ ull ffma2(ull a, ull b, ull c) {
    ull d; asm("fma.rn.f32x2 %0, %1, %2, %3;" : "=l"(d) : "l"(a), "l"(b), "l"(c));
    return d;
}
__device__ __forceinline__ ull fadd2(ull a, ull b) {
    ull d; asm("add.rn.f32x2 %0, %1, %2;" : "=l"(d) : "l"(a), "l"(b));
    return d;
}
__device__ __forceinline__ ull pack2(float x) {
    ull d; uint32_t t = __float_as_uint(x);
    asm("mov.b64 %0, {%1, %2};" : "=l"(d) : "r"(t), "r"(t));
    return d;
}
__device__ __forceinline__ ull pack2two(float a, float b) {
    ull d;
    asm("mov.b64 %0, {%1, %2};" : "=l"(d)
        : "r"(__float_as_uint(a)), "r"(__float_as_uint(b)));
    return d;
}
__device__ __forceinline__ void unpack2(ull v, float& a, float& b) {
    uint32_t lo, hi;
    asm("mov.b64 {%0, %1}, %2;" : "=r"(lo), "=r"(hi) : "l"(v));
    a = __uint_as_float(lo); b = __uint_as_float(hi);
}
__device__ __forceinline__ float hadd2(ull v) {
    float a, b; unpack2(v, a, b); return a + b;
}

__global__ void __launch_bounds__(NTHREADS, 1)
rls_kernel(const float* __restrict__ x_seq,
           const float* __restrict__ d_seq,
           const float* __restrict__ lambdas,
           float* __restrict__ y_out,
           float* __restrict__ w_out)
{
    const int b    = blockIdx.x;
    const int tid  = threadIdx.x;
    const int i    = tid >> 1;   // row 0..63
    const int c    = tid & 1;    // column-half 0/1 (== lane parity)
    const int lane = tid & 31;
    const int warp = tid >> 5;

    __shared__ __align__(16) float xc[4][CHUNK][TAPS];   // rotating chunk bufs
    __shared__ __align__(16) float dc[4][CHUNK];
    __shared__ __align__(16) float lc[4][CHUNK];
    __shared__ __align__(16) float ub[2][4][TAPS];       // u1..u4, ping-pong
    __shared__ __align__(16) float4 redE[2][4][2];       // even-lane sums per warp
    __shared__ __align__(16) float4 redO[2][4][2];       // odd-lane sums per warp
    __shared__ float tile[TAPS][TAPS + 1];

    // Q row-half packed: 16 x f32x2 (cols [32c,32c+32)).  P = Q / rho.
    ull Q2[16];
#pragma unroll
    for (int k = 0; k < 16; k++) {
        const int j0 = c * 32 + 2 * k;
        Q2[k] = pack2two(i == j0 ? 1.0f : 0.0f, i == j0 + 1 ? 1.0f : 0.0f);
    }
    float wi  = 0.0f;    // w_i row scalar (identical on both c threads)
    float rho = 1.0f;    // rho = prod(lambda) = 1/sigma

    const float* xgb = x_seq + (size_t)b * NSTEPS * TAPS;
    const float* dgb = d_seq + (size_t)b * NSTEPS;
    float* yo = y_out + (size_t)b * NSTEPS;

    const uint32_t xc_s = (uint32_t)__cvta_generic_to_shared(&xc[0][0][0]);
    const uint32_t dc_s = (uint32_t)__cvta_generic_to_shared(&dc[0][0]);
    const uint32_t lc_s = (uint32_t)__cvta_generic_to_shared(&lc[0][0]);

    auto issue_chunk = [&](int ck, int cb) {
#pragma unroll
        for (int j = 0; j < 2; j++)
            cp16(xc_s + (uint32_t)(cb * (CHUNK * TAPS) + j * 512) * 4 + tid * 16,
                 xgb + (size_t)ck * CHUNK * TAPS + j * 512 + tid * 4);
        if (tid < 4)
            cp16(dc_s + (uint32_t)(cb * CHUNK) * 4 + tid * 16,
                 dgb + ck * CHUNK + tid * 4);
        else if (tid < 8)
            cp16(lc_s + (uint32_t)(cb * CHUNK) * 4 + (tid - 4) * 16,
                 lambdas + ck * CHUNK + (tid - 4) * 4);
        cp_commit();
    };

    issue_chunk(0, 0);
    issue_chunk(1, 1);
    cp_wait<1>();
    __syncthreads();

    for (int ck = 0; ck < NCHUNK; ck++) {
        if (ck + 2 < NCHUNK) { issue_chunk(ck + 2, (ck + 2) & 3); cp_wait<1>(); }
        else                 { cp_wait<0>(); }
        __syncthreads();
        const int cb = ck & 3;

        // 4 rank-4 blocks per chunk (steps 4m .. 4m+3)
#pragma unroll
        for (int blk = 0; blk < CHUNK / 4; blk++) {
            const int s  = 4 * blk;
            const int t  = ck * CHUNK + s;
            const int pb = blk & 1;

            const float* xp = &xc[cb][s][0];   // rows s..s+3 contiguous

            // ===== Phase A: u_j = Q x_j, j = 1..4 =====
            ull a1 = 0ull, b1 = 0ull, a2 = 0ull, b2 = 0ull;
            ull a3 = 0ull, b3 = 0ull, a4 = 0ull, b4 = 0ull;
#pragma unroll
            for (int k = 0; k < 8; k++) {
                const ulonglong2 v1 = *(const ulonglong2*)(xp + 0 * TAPS + c * 32 + 4 * k);
                const ulonglong2 v2 = *(const ulonglong2*)(xp + 1 * TAPS + c * 32 + 4 * k);
                const ulonglong2 v3 = *(const ulonglong2*)(xp + 2 * TAPS + c * 32 + 4 * k);
                const ulonglong2 v4 = *(const ulonglong2*)(xp + 3 * TAPS + c * 32 + 4 * k);
                a1 = ffma2(Q2[2 * k], v1.x, a1); b1 = ffma2(Q2[2 * k + 1], v1.y, b1);
                a2 = ffma2(Q2[2 * k], v2.x, a2); b2 = ffma2(Q2[2 * k + 1], v2.y, b2);
                a3 = ffma2(Q2[2 * k], v3.x, a3); b3 = ffma2(Q2[2 * k + 1], v3.y, b3);
                a4 = ffma2(Q2[2 * k], v4.x, a4); b4 = ffma2(Q2[2 * k + 1], v4.y, b4);
            }
            float u1i = hadd2(fadd2(a1, b1));
            float u2i = hadd2(fadd2(a2, b2));
            float u3i = hadd2(fadd2(a3, b3));
            float u4i = hadd2(fadd2(a4, b4));
            u1i += __shfl_xor_sync(0xffffffffu, u1i, 1);
            u2i += __shfl_xor_sync(0xffffffffu, u2i, 1);
            u3i += __shfl_xor_sync(0xffffffffu, u3i, 1);
            u4i += __shfl_xor_sync(0xffffffffu, u4i, 1);
            if (c == 0) {
                ub[pb][0][i] = u1i; ub[pb][1][i] = u2i;
                ub[pb][2][i] = u3i; ub[pb][3][i] = u4i;
            }

            // ===== 14 block scalars via 7 parity trees =====
            const float x1i = xp[i];
            const float x2i = xp[TAPS + i];
            const float x3i = xp[2 * TAPS + i];
            const float x4i = xp[3 * TAPS + i];
            float T1 = (c == 0) ? u1i * x1i : u1i * x2i;   // G11 | G12
            float T2 = (c == 0) ? u1i * x3i : u1i * x4i;   // G13 | G14
            float T3 = (c == 0) ? u2i * x2i : u2i * x3i;   // G22 | G23
            float T4 = (c == 0) ? u2i * x4i : u3i * x3i;   // G24 | G33
            float T5 = (c == 0) ? u3i * x4i : u4i * x4i;   // G34 | G44
            float T6 = (c == 0) ? wi  * x1i : wi  * x2i;   // W1  | W2
            float T7 = (c == 0) ? wi  * x3i : wi  * x4i;   // W3  | W4
#pragma unroll
            for (int off = 16; off >= 2; off >>= 1) {
                T1 += __shfl_xor_sync(0xffffffffu, T1, off);
                T2 += __shfl_xor_sync(0xffffffffu, T2, off);
                T3 += __shfl_xor_sync(0xffffffffu, T3, off);
                T4 += __shfl_xor_sync(0xffffffffu, T4, off);
                T5 += __shfl_xor_sync(0xffffffffu, T5, off);
                T6 += __shfl_xor_sync(0xffffffffu, T6, off);
                T7 += __shfl_xor_sync(0xffffffffu, T7, off);
            }
            if (lane == 0) {
                redE[pb][warp][0] = make_float4(T1, T2, T3, T4);
                redE[pb][warp][1] = make_float4(T5, T6, T7, 0.0f);
            }
            if (lane == 1) {
                redO[pb][warp][0] = make_float4(T1, T2, T3, T4);
                redO[pb][warp][1] = make_float4(T5, T6, T7, 0.0f);
            }

            const float d1 = dc[cb][s],     d2 = dc[cb][s + 1];
            const float d3 = dc[cb][s + 2], d4 = dc[cb][s + 3];
            const float l1 = fminf(fmaxf(lc[cb][s],     1e-4f), 0.9999f);
            const float l2 = fminf(fmaxf(lc[cb][s + 1], 1e-4f), 0.9999f);
            const float l3 = fminf(fmaxf(lc[cb][s + 2], 1e-4f), 0.9999f);
            const float l4 = fminf(fmaxf(lc[cb][s + 3], 1e-4f), 0.9999f);

            __syncthreads();   // the ONE barrier per 4 steps

            // ===== Phase B: combine =====
            const float4 E00 = redE[pb][0][0], E01 = redE[pb][0][1];
            const float4 E10 = redE[pb][1][0], E11 = redE[pb][1][1];
            const float4 E20 = redE[pb][2][0], E21 = redE[pb][2][1];
            const float4 E30 = redE[pb][3][0], E31 = redE[pb][3][1];
            const float4 O00 = redO[pb][0][0], O01 = redO[pb][0][1];
            const float4 O10 = redO[pb][1][0], O11 = redO[pb][1][1];
            const float4 O20 = redO[pb][2][0], O21 = redO[pb][2][1];
            const float4 O30 = redO[pb][3][0], O31 = redO[pb][3][1];
            const float G11 = (E00.x + E10.x) + (E20.x + E30.x);
            const float G13 = (E00.y + E10.y) + (E20.y + E30.y);
            const float G22 = (E00.z + E10.z) + (E20.z + E30.z);
            const float G24 = (E00.w + E10.w) + (E20.w + E30.w);
            const float G34 = (E01.x + E11.x) + (E21.x + E31.x);
            const float W1  = (E01.y + E11.y) + (E21.y + E31.y);
            const float W3  = (E01.z + E11.z) + (E21.z + E31.z);
            const float G12 = (O00.x + O10.x) + (O20.x + O30.x);
            const float G14 = (O00.y + O10.y) + (O20.y + O30.y);
            const float G23 = (O00.z + O10.z) + (O20.z + O30.z);
            const float G33 = (O00.w + O10.w) + (O20.w + O30.w);
            const float G44 = (O01.x + O11.x) + (O21.x + O31.x);
            const float W2  = (O01.y + O11.y) + (O21.y + O31.y);
            const float W4  = (O01.z + O11.z) + (O21.z + O31.z);

            // ===== sequential scalar RLS on Gram entries =====
            const float P1 = rho * l1, P2 = P1 * l2, P3 = P2 * l3, P4 = P3 * l4;
            const float k1 = __fdividef(1.0f, P1 + G11);
            const float e1 = d1 - W1;
            const float g22 = fmaf(-k1 * G12, G12, G22);
            const float g23 = fmaf(-k1 * G12, G13, G23);
            const float g24 = fmaf(-k1 * G12, G14, G24);
            const float k2 = __fdividef(1.0f, P2 + g22);
            const float y2 = fmaf(k1 * e1, G12, W2);
            const float e2 = d2 - y2;
            const float g33 = fmaf(-k2 * g23, g23, fmaf(-k1 * G13, G13, G33));
            const float g34 = fmaf(-k2 * g23, g24, fmaf(-k1 * G13, G14, G34));
            const float k3 = __fdividef(1.0f, P3 + g33);
            const float y3 = fmaf(k2 * e2, g23, fmaf(k1 * e1, G13, W3));
            const float e3 = d3 - y3;
            const float g44 = fmaf(-k3 * g34, g34,
                             fmaf(-k2 * g24, g24, fmaf(-k1 * G14, G14, G44)));
            const float k4 = __fdividef(1.0f, P4 + g44);
            const float y4 = fmaf(k3 * e3, g34,
                             fmaf(k2 * e2, g24, fmaf(k1 * e1, G14, W4)));
            const float e4 = d4 - y4;
            rho = P4;
            if (tid == 0) { yo[t] = W1; yo[t + 1] = y2; yo[t + 2] = y3; yo[t + 3] = y4; }

            // ===== mu coefficients (uhat_m = sum_j mu_mj u_j) =====
            const float mu21 = -k1 * G12;
            const float mu31 = fmaf(-k2 * g23, mu21, -k1 * G13);
            const float mu32 = -k2 * g23;
            const float mu41 = fmaf(-k3 * g34, mu31, fmaf(-k2 * g24, mu21, -k1 * G14));
            const float mu42 = fmaf(-k3 * g34, mu32, -k2 * g24);
            const float mu43 = -k3 * g34;

            // ===== C = sum_m k_m mu_m mu_m' (4x4 sym) =====
            const float C11 = k1 + k2 * mu21 * mu21 + k3 * mu31 * mu31 + k4 * mu41 * mu41;
            const float C12 = k2 * mu21 + k3 * mu31 * mu32 + k4 * mu41 * mu42;
            const float C13 = k3 * mu31 + k4 * mu41 * mu43;
            const float C14 = k4 * mu41;
            const float C22 = k2 + k3 * mu32 * mu32 + k4 * mu42 * mu42;
            const float C23 = k3 * mu32 + k4 * mu42 * mu43;
            const float C24 = k4 * mu42;
            const float C33 = k3 + k4 * mu43 * mu43;
            const float C34 = k4 * mu43;
            const float C44 = k4;

            // ===== w row-scalar update: w += sum_j omega_j u_j =====
            const float k1e1 = k1 * e1, k2e2 = k2 * e2, k3e3 = k3 * e3, k4e4 = k4 * e4;
            const float om1 = k1e1 + k2e2 * mu21 + k3e3 * mu31 + k4e4 * mu41;
            const float om2 = k2e2 + k3e3 * mu32 + k4e4 * mu42;
            const float om3 = k3e3 + k4e4 * mu43;
            const float om4 = k4e4;
            wi = fmaf(om1, u1i, fmaf(om2, u2i, fmaf(om3, u3i, fmaf(om4, u4i, wi))));

            // ===== Q -= U C U': row coeffs r_n = sum_m C_mn u_m,i =====
            const float r1 = C11 * u1i + C12 * u2i + C13 * u3i + C14 * u4i;
            const float r2 = C12 * u1i + C22 * u2i + C23 * u3i + C24 * u4i;
            const float r3 = C13 * u1i + C23 * u2i + C33 * u3i + C34 * u4i;
            const float r4 = C14 * u1i + C24 * u2i + C34 * u3i + C44 * u4i;
            const ull nr1 = pack2(-r1), nr2 = pack2(-r2);
            const ull nr3 = pack2(-r3), nr4 = pack2(-r4);
#pragma unroll
            for (int k = 0; k < 8; k++) {
                const ulonglong2 uu1 = *(const ulonglong2*)(&ub[pb][0][c * 32 + 4 * k]);
                const ulonglong2 uu2 = *(const ulonglong2*)(&ub[pb][1][c * 32 + 4 * k]);
                const ulonglong2 uu3 = *(const ulonglong2*)(&ub[pb][2][c * 32 + 4 * k]);
                const ulonglong2 uu4 = *(const ulonglong2*)(&ub[pb][3][c * 32 + 4 * k]);
                ull qa = Q2[2 * k], qb = Q2[2 * k + 1];
                qa = ffma2(nr1, uu1.x, qa); qb = ffma2(nr1, uu1.y, qb);
                qa = ffma2(nr2, uu2.x, qa); qb = ffma2(nr2, uu2.y, qb);
                qa = ffma2(nr3, uu3.x, qa); qb = ffma2(nr3, uu3.y, qb);
                qa = ffma2(nr4, uu4.x, qa); qb = ffma2(nr4, uu4.y, qb);
                Q2[2 * k] = qa; Q2[2 * k + 1] = qb;
            }
        }

        // ---- symmetrize every SYM_CHUNKS chunks (kills undamped antisym mode) ----
        if ((ck % SYM_CHUNKS) == (SYM_CHUNKS - 1)) {
            __syncthreads();
#pragma unroll
            for (int k = 0; k < 16; k++) {
                float f0, f1; unpack2(Q2[k], f0, f1);
                tile[i][c * 32 + 2 * k]     = f0;
                tile[i][c * 32 + 2 * k + 1] = f1;
            }
            __syncthreads();
#pragma unroll
            for (int k = 0; k < 16; k++) {
                float f0, f1; unpack2(Q2[k], f0, f1);
                const float t0 = tile[c * 32 + 2 * k][i];
                const float t1 = tile[c * 32 + 2 * k + 1][i];
                Q2[k] = pack2two(0.5f * (f0 + t0), 0.5f * (f1 + t1));
            }
            __syncthreads();
        }
    }

    // ---- outputs: w_i row scalars ----
    if (c == 0) w_out[(size_t)b * TAPS + i] = wi;
}

extern "C" void kernel_launch(void* const* d_in, const int* in_sizes, int n_in,
                              void* d_out, int out_size)
{
    const float* x_seq   = (const float*)d_in[0];
    const float* d_seq   = (const float*)d_in[1];
    const float* lambdas = (const float*)d_in[2];
    float* y_out = (float*)d_out;                          // [64, 2000]
    float* w_out = (float*)d_out + (size_t)BATCH * NSTEPS; // [64, 64]
    rls_kernel<<<BATCH, NTHREADS>>>(x_seq, d_seq, lambdas, y_out, w_out);
}

// round 16
// speedup vs baseline: 1.8868x; 1.0094x over previous
#include <cuda_runtime.h>
#include <cstdint>

#define BATCH 64
#define NSTEPS 2000
#define TAPS 64
#define NTHREADS 128
#define CHUNK 16
#define NCHUNK (NSTEPS / CHUNK)   // 125
#define SYM_CHUNKS 6              // symmetrize every 96 steps

using ull = unsigned long long;

__device__ __forceinline__ void cp16(uint32_t dst_smem, const void* src_gmem) {
    asm volatile("cp.async.cg.shared.global [%0], [%1], 16;\n"
                 :: "r"(dst_smem), "l"(src_gmem));
}
__device__ __forceinline__ void cp_commit() {
    asm volatile("cp.async.commit_group;\n");
}
template <int N>
__device__ __forceinline__ void cp_wait() {
    asm volatile("cp.async.wait_group %0;\n" :: "n"(N));
}

// ---- packed f32x2 ops (Blackwell sm_103a) ----
__device__ __forceinline__ ull ffma2(ull a, ull b, ull c) {
    ull d; asm("fma.rn.f32x2 %0, %1, %2, %3;" : "=l"(d) : "l"(a), "l"(b), "l"(c));
    return d;
}
__device__ __forceinline__ ull fadd2(ull a, ull b) {
    ull d; asm("add.rn.f32x2 %0, %1, %2;" : "=l"(d) : "l"(a), "l"(b));
    return d;
}
__device__ __forceinline__ ull pack2(float x) {
    ull d; uint32_t t = __float_as_uint(x);
    asm("mov.b64 %0, {%1, %2};" : "=l"(d) : "r"(t), "r"(t));
    return d;
}
__device__ __forceinline__ ull pack2two(float a, float b) {
    ull d;
    asm("mov.b64 %0, {%1, %2};" : "=l"(d)
        : "r"(__float_as_uint(a)), "r"(__float_as_uint(b)));
    return d;
}
__device__ __forceinline__ void unpack2(ull v, float& a, float& b) {
    uint32_t lo, hi;
    asm("mov.b64 {%0, %1}, %2;" : "=r"(lo), "=r"(hi) : "l"(v));
    a = __uint_as_float(lo); b = __uint_as_float(hi);
}
__device__ __forceinline__ float hadd2(ull v) {
    float a, b; unpack2(v, a, b); return a + b;
}

__global__ void __launch_bounds__(NTHREADS, 1)
rls_kernel(const float* __restrict__ x_seq,
           const float* __restrict__ d_seq,
           const float* __restrict__ lambdas,
           float* __restrict__ y_out,
           float* __restrict__ w_out)
{
    const int b    = blockIdx.x;
    const int tid  = threadIdx.x;
    const int i    = tid >> 1;   // row 0..63
    const int c    = tid & 1;    // column-half 0/1 (== lane parity)
    const int lane = tid & 31;
    const int warp = tid >> 5;

    __shared__ __align__(16) float xc[4][CHUNK][TAPS];   // rotating chunk bufs
    __shared__ __align__(16) float dc[4][CHUNK];
    __shared__ __align__(16) float lc[4][CHUNK];
    __shared__ __align__(16) float ub[2][4][TAPS];       // u1..u4, ping-pong
    __shared__ __align__(32) float4 redE[2][4][2];       // even-lane sums per warp
    __shared__ __align__(32) float4 redO[2][4][2];       // odd-lane sums per warp
    __shared__ float tile[TAPS][TAPS + 1];

    // Q row-half packed: 16 x f32x2 (cols [32c,32c+32)).  P = Q / rho.
    ull Q2[16];
#pragma unroll
    for (int k = 0; k < 16; k++) {
        const int j0 = c * 32 + 2 * k;
        Q2[k] = pack2two(i == j0 ? 1.0f : 0.0f, i == j0 + 1 ? 1.0f : 0.0f);
    }
    float wi  = 0.0f;    // w_i row scalar (identical on both c threads)
    float rho = 1.0f;    // rho = prod(lambda) = 1/sigma

    const float* xgb = x_seq + (size_t)b * NSTEPS * TAPS;
    const float* dgb = d_seq + (size_t)b * NSTEPS;
    float* yo = y_out + (size_t)b * NSTEPS;

    const uint32_t xc_s = (uint32_t)__cvta_generic_to_shared(&xc[0][0][0]);
    const uint32_t dc_s = (uint32_t)__cvta_generic_to_shared(&dc[0][0]);
    const uint32_t lc_s = (uint32_t)__cvta_generic_to_shared(&lc[0][0]);

    auto issue_chunk = [&](int ck, int cb) {
#pragma unroll
        for (int j = 0; j < 2; j++)
            cp16(xc_s + (uint32_t)(cb * (CHUNK * TAPS) + j * 512) * 4 + tid * 16,
                 xgb + (size_t)ck * CHUNK * TAPS + j * 512 + tid * 4);
        if (tid < 4)
            cp16(dc_s + (uint32_t)(cb * CHUNK) * 4 + tid * 16,
                 dgb + ck * CHUNK + tid * 4);
        else if (tid < 8)
            cp16(lc_s + (uint32_t)(cb * CHUNK) * 4 + (tid - 4) * 16,
                 lambdas + ck * CHUNK + (tid - 4) * 4);
        cp_commit();
    };

    issue_chunk(0, 0);
    issue_chunk(1, 1);
    cp_wait<1>();
    __syncthreads();

    for (int ck = 0; ck < NCHUNK; ck++) {
        if (ck + 2 < NCHUNK) { issue_chunk(ck + 2, (ck + 2) & 3); cp_wait<1>(); }
        else                 { cp_wait<0>(); }
        __syncthreads();
        const int cb = ck & 3;

        // 4 rank-4 blocks per chunk (steps 4m .. 4m+3)
#pragma unroll
        for (int blk = 0; blk < CHUNK / 4; blk++) {
            const int s  = 4 * blk;
            const int t  = ck * CHUNK + s;
            const int pb = blk & 1;

            const float* xp = &xc[cb][s][0];   // rows s..s+3 contiguous

            // ===== Phase A: u_j = Q x_j, j = 1..4 =====
            ull a1 = 0ull, b1 = 0ull, a2 = 0ull, b2 = 0ull;
            ull a3 = 0ull, b3 = 0ull, a4 = 0ull, b4 = 0ull;
#pragma unroll
            for (int k = 0; k < 8; k++) {
                const ulonglong2 v1 = *(const ulonglong2*)(xp + 0 * TAPS + c * 32 + 4 * k);
                const ulonglong2 v2 = *(const ulonglong2*)(xp + 1 * TAPS + c * 32 + 4 * k);
                const ulonglong2 v3 = *(const ulonglong2*)(xp + 2 * TAPS + c * 32 + 4 * k);
                const ulonglong2 v4 = *(const ulonglong2*)(xp + 3 * TAPS + c * 32 + 4 * k);
                a1 = ffma2(Q2[2 * k], v1.x, a1); b1 = ffma2(Q2[2 * k + 1], v1.y, b1);
                a2 = ffma2(Q2[2 * k], v2.x, a2); b2 = ffma2(Q2[2 * k + 1], v2.y, b2);
                a3 = ffma2(Q2[2 * k], v3.x, a3); b3 = ffma2(Q2[2 * k + 1], v3.y, b3);
                a4 = ffma2(Q2[2 * k], v4.x, a4); b4 = ffma2(Q2[2 * k + 1], v4.y, b4);
            }
            float u1i = hadd2(fadd2(a1, b1));
            float u2i = hadd2(fadd2(a2, b2));
            float u3i = hadd2(fadd2(a3, b3));
            float u4i = hadd2(fadd2(a4, b4));
            u1i += __shfl_xor_sync(0xffffffffu, u1i, 1);
            u2i += __shfl_xor_sync(0xffffffffu, u2i, 1);
            u3i += __shfl_xor_sync(0xffffffffu, u3i, 1);
            u4i += __shfl_xor_sync(0xffffffffu, u4i, 1);
            if (c == 0) {
                ub[pb][0][i] = u1i; ub[pb][1][i] = u2i;
                ub[pb][2][i] = u3i; ub[pb][3][i] = u4i;
            }

            // ===== 14 block scalars via 7 parity trees =====
            const float x1i = xp[i];
            const float x2i = xp[TAPS + i];
            const float x3i = xp[2 * TAPS + i];
            const float x4i = xp[3 * TAPS + i];
            float T1 = (c == 0) ? u1i * x1i : u1i * x2i;   // G11 | G12
            float T2 = (c == 0) ? u1i * x3i : u1i * x4i;   // G13 | G14
            float T3 = (c == 0) ? u2i * x2i : u2i * x3i;   // G22 | G23
            float T4 = (c == 0) ? u2i * x4i : u3i * x3i;   // G24 | G33
            float T5 = (c == 0) ? u3i * x4i : u4i * x4i;   // G34 | G44
            float T6 = (c == 0) ? wi  * x1i : wi  * x2i;   // W1  | W2
            float T7 = (c == 0) ? wi  * x3i : wi  * x4i;   // W3  | W4
#pragma unroll
            for (int off = 16; off >= 2; off >>= 1) {
                T1 += __shfl_xor_sync(0xffffffffu, T1, off);
                T2 += __shfl_xor_sync(0xffffffffu, T2, off);
                T3 += __shfl_xor_sync(0xffffffffu, T3, off);
                T4 += __shfl_xor_sync(0xffffffffu, T4, off);
                T5 += __shfl_xor_sync(0xffffffffu, T5, off);
                T6 += __shfl_xor_sync(0xffffffffu, T6, off);
                T7 += __shfl_xor_sync(0xffffffffu, T7, off);
            }
            if (lane == 0) {
                redE[pb][warp][0] = make_float4(T1, T2, T3, T4);
                redE[pb][warp][1] = make_float4(T5, T6, T7, 0.0f);
            }
            if (lane == 1) {
                redO[pb][warp][0] = make_float4(T1, T2, T3, T4);
                redO[pb][warp][1] = make_float4(T5, T6, T7, 0.0f);
            }

            const float d1 = dc[cb][s],     d2 = dc[cb][s + 1];
            const float d3 = dc[cb][s + 2], d4 = dc[cb][s + 3];
            const float l1 = fminf(fmaxf(lc[cb][s],     1e-4f), 0.9999f);
            const float l2 = fminf(fmaxf(lc[cb][s + 1], 1e-4f), 0.9999f);
            const float l3 = fminf(fmaxf(lc[cb][s + 2], 1e-4f), 0.9999f);
            const float l4 = fminf(fmaxf(lc[cb][s + 3], 1e-4f), 0.9999f);

            __syncthreads();   // the ONE barrier per 4 steps

            // ===== Phase B: packed combine (f32x2 adds) =====
            const ulonglong2* rE = (const ulonglong2*)&redE[pb][0][0];
            const ulonglong2* rO = (const ulonglong2*)&redO[pb][0][0];
            const ulonglong2 e0 = rE[0], e1v = rE[2], e2v = rE[4], e3v = rE[6];
            const ulonglong2 f0 = rE[1], f1v = rE[3], f2v = rE[5], f3v = rE[7];
            const ulonglong2 o0 = rO[0], o1v = rO[2], o2v = rO[4], o3v = rO[6];
            const ulonglong2 p0 = rO[1], p1v = rO[3], p2v = rO[5], p3v = rO[7];
            const ull E0 = fadd2(fadd2(e0.x, e1v.x), fadd2(e2v.x, e3v.x));
            const ull E1 = fadd2(fadd2(e0.y, e1v.y), fadd2(e2v.y, e3v.y));
            const ull E2 = fadd2(fadd2(f0.x, f1v.x), fadd2(f2v.x, f3v.x));
            const ull E3 = fadd2(fadd2(f0.y, f1v.y), fadd2(f2v.y, f3v.y));
            const ull O0 = fadd2(fadd2(o0.x, o1v.x), fadd2(o2v.x, o3v.x));
            const ull O1 = fadd2(fadd2(o0.y, o1v.y), fadd2(o2v.y, o3v.y));
            const ull O2 = fadd2(fadd2(p0.x, p1v.x), fadd2(p2v.x, p3v.x));
            const ull O3 = fadd2(fadd2(p0.y, p1v.y), fadd2(p2v.y, p3v.y));
            float G11, G13; unpack2(E0, G11, G13);
            float G22, G24; unpack2(E1, G22, G24);
            float G34, W1;  unpack2(E2, G34, W1);
            float W3, pe;   unpack2(E3, W3, pe);
            float G12, G14; unpack2(O0, G12, G14);
            float G23, G33; unpack2(O1, G23, G33);
            float G44, W2;  unpack2(O2, G44, W2);
            float W4, po;   unpack2(O3, W4, po);

            // ===== gains via leading principal minors (parallel, no chain) =====
            const float P1 = rho * l1, P2 = P1 * l2, P3 = P2 * l3, P4 = P3 * l4;
            const float sa = P1 + G11, se = P2 + G22, sh = P3 + G33, sj = P4 + G44;
            const float ra = __fdividef(1.0f, sa);
            // normalized S' = ra * S  (S'11 = 1); dets O(1)
            const float bp2 = G12 * ra, cp2 = G13 * ra, dp2 = G14 * ra;
            const float ep2 = se  * ra, fp2 = G23 * ra, gp2 = G24 * ra;
            const float hp2 = sh  * ra, ip2 = G34 * ra, jp2 = sj  * ra;
            const float det2p = fmaf(-bp2, bp2, ep2);
            const float det3p = fmaf(ep2, fmaf(hp2, 1.0f, 0.0f) * 0.0f + hp2, 0.0f) * 0.0f
                              + (ep2 * hp2 - fp2 * fp2)
                              - bp2 * (bp2 * hp2 - fp2 * cp2)
                              + cp2 * (bp2 * fp2 - ep2 * cp2);
            const float m1 = fmaf(hp2, jp2, -ip2 * ip2);
            const float m2 = fmaf(fp2, jp2, -gp2 * ip2);
            const float m3 = fmaf(fp2, ip2, -gp2 * hp2);
            const float n1 = fmaf(cp2, jp2, -dp2 * ip2);
            const float n2 = fmaf(cp2, ip2, -dp2 * hp2);
            const float n3 = fmaf(cp2, gp2, -dp2 * fp2);
            const float detL = ep2 * m1 - fp2 * m2 + gp2 * m3;
            const float D2c  = bp2 * m1 - fp2 * n1 + gp2 * n2;
            const float D3c  = bp2 * m2 - ep2 * n1 + gp2 * n3;
            const float D4c  = bp2 * m3 - ep2 * n2 + fp2 * n3;
            const float det4p = detL - bp2 * D2c + cp2 * D3c - dp2 * D4c;
            const float k1 = ra;
            const float k2 = ra * __fdividef(1.0f, det2p);
            const float k3 = ra * det2p * __fdividef(1.0f, det3p);
            const float k4 = ra * det3p * __fdividef(1.0f, det4p);
            rho = P4;

            // ===== updated off-diag Schur entries (shallow; k's already known) ====
            const float g23 = fmaf(-k1 * G12, G13, G23);
            const float g24 = fmaf(-k1 * G12, G14, G24);
            const float g34 = fmaf(-k2 * g23, g24, fmaf(-k1 * G13, G14, G34));

            // ===== y / e chain (short serial) =====
            const float e1 = d1 - W1;
            const float y2 = fmaf(k1 * e1, G12, W2);
            const float e2 = d2 - y2;
            const float y3 = fmaf(k2 * e2, g23, fmaf(k1 * e1, G13, W3));
            const float e3 = d3 - y3;
            const float y4 = fmaf(k3 * e3, g34,
                             fmaf(k2 * e2, g24, fmaf(k1 * e1, G14, W4)));
            const float e4 = d4 - y4;
            if (tid == 0) { yo[t] = W1; yo[t + 1] = y2; yo[t + 2] = y3; yo[t + 3] = y4; }

            // ===== mu coefficients (uhat_m = sum_j mu_mj u_j) =====
            const float mu21 = -k1 * G12;
            const float mu31 = fmaf(-k2 * g23, mu21, -k1 * G13);
            const float mu32 = -k2 * g23;
            const float mu41 = fmaf(-k3 * g34, mu31, fmaf(-k2 * g24, mu21, -k1 * G14));
            const float mu42 = fmaf(-k3 * g34, mu32, -k2 * g24);
            const float mu43 = -k3 * g34;

            // ===== C = sum_m k_m mu_m mu_m' (4x4 sym) =====
            const float C11 = k1 + k2 * mu21 * mu21 + k3 * mu31 * mu31 + k4 * mu41 * mu41;
            const float C12 = k2 * mu21 + k3 * mu31 * mu32 + k4 * mu41 * mu42;
            const float C13 = k3 * mu31 + k4 * mu41 * mu43;
            const float C14 = k4 * mu41;
            const float C22 = k2 + k3 * mu32 * mu32 + k4 * mu42 * mu42;
            const float C23 = k3 * mu32 + k4 * mu42 * mu43;
            const float C24 = k4 * mu42;
            const float C33 = k3 + k4 * mu43 * mu43;
            const float C34 = k4 * mu43;
            const float C44 = k4;

            // ===== w row-scalar update: w += sum_j omega_j u_j =====
            const float k1e1 = k1 * e1, k2e2 = k2 * e2, k3e3 = k3 * e3, k4e4 = k4 * e4;
            const float om1 = k1e1 + k2e2 * mu21 + k3e3 * mu31 + k4e4 * mu41;
            const float om2 = k2e2 + k3e3 * mu32 + k4e4 * mu42;
            const float om3 = k3e3 + k4e4 * mu43;
            const float om4 = k4e4;
            wi = fmaf(om1, u1i, fmaf(om2, u2i, fmaf(om3, u3i, fmaf(om4, u4i, wi))));

            // ===== Q -= U C U': row coeffs r_n = sum_m C_mn u_m,i =====
            const float r1 = C11 * u1i + C12 * u2i + C13 * u3i + C14 * u4i;
            const float r2 = C12 * u1i + C22 * u2i + C23 * u3i + C24 * u4i;
            const float r3 = C13 * u1i + C23 * u2i + C33 * u3i + C34 * u4i;
            const float r4 = C14 * u1i + C24 * u2i + C34 * u3i + C44 * u4i;
            const ull nr1 = pack2(-r1), nr2 = pack2(-r2);
            const ull nr3 = pack2(-r3), nr4 = pack2(-r4);
#pragma unroll
            for (int k = 0; k < 8; k++) {
                const ulonglong2 uu1 = *(const ulonglong2*)(&ub[pb][0][c * 32 + 4 * k]);
                const ulonglong2 uu2 = *(const ulonglong2*)(&ub[pb][1][c * 32 + 4 * k]);
                const ulonglong2 uu3 = *(const ulonglong2*)(&ub[pb][2][c * 32 + 4 * k]);
                const ulonglong2 uu4 = *(const ulonglong2*)(&ub[pb][3][c * 32 + 4 * k]);
                ull qa = Q2[2 * k], qb = Q2[2 * k + 1];
                qa = ffma2(nr1, uu1.x, qa); qb = ffma2(nr1, uu1.y, qb);
                qa = ffma2(nr2, uu2.x, qa); qb = ffma2(nr2, uu2.y, qb);
                qa = ffma2(nr3, uu3.x, qa); qb = ffma2(nr3, uu3.y, qb);
                qa = ffma2(nr4, uu4.x, qa); qb = ffma2(nr4, uu4.y, qb);
                Q2[2 * k] = qa; Q2[2 * k + 1] = qb;
            }
        }

        // ---- symmetrize every SYM_CHUNKS chunks (kills undamped antisym mode) ----
        if ((ck % SYM_CHUNKS) == (SYM_CHUNKS - 1)) {
            __syncthreads();
#pragma unroll
            for (int k = 0; k < 16; k++) {
                float f0, f1; unpack2(Q2[k], f0, f1);
                tile[i][c * 32 + 2 * k]     = f0;
                tile[i][c * 32 + 2 * k + 1] = f1;
            }
            __syncthreads();
#pragma unroll
            for (int k = 0; k < 16; k++) {
                float f0, f1; unpack2(Q2[k], f0, f1);
                const float t0 = tile[c * 32 + 2 * k][i];
                const float t1 = tile[c * 32 + 2 * k + 1][i];
                Q2[k] = pack2two(0.5f * (f0 + t0), 0.5f * (f1 + t1));
            }
            __syncthreads();
        }
    }

    // ---- outputs: w_i row scalars ----
    if (c == 0) w_out[(size_t)b * TAPS + i] = wi;
}

extern "C" void kernel_launch(void* const* d_in, const int* in_sizes, int n_in,
                              void* d_out, int out_size)
{
    const float* x_seq   = (const float*)d_in[0];
    const float* d_seq   = (const float*)d_in[1];
    const float* lambdas = (const float*)d_in[2];
    float* y_out = (float*)d_out;                          // [64, 2000]
    float* w_out = (float*)d_out + (size_t)BATCH * NSTEPS; // [64, 64]
    rls_kernel<<<BATCH, NTHREADS>>>(x_seq, d_seq, lambdas, y_out, w_out);
}